// round 1
// baseline (speedup 1.0000x reference)
#include <cuda_runtime.h>
#include <cuda_bf16.h>
#include <math.h>

// Problem constants
#define BB   2
#define TT   2048
#define DD   2048
#define HH   32
#define KVH  8
#define HD   64
#define GG   4
#define MTOT (BB*TT)      // 4096
#define DKV  (KVH*HD)     // 512

// Scratch (allocation-free rule: __device__ globals)
__device__ float g_Q[(size_t)MTOT * DD];
__device__ float g_K[(size_t)MTOT * DKV];
__device__ float g_V[(size_t)MTOT * DKV];
__device__ float g_A[(size_t)MTOT * DD];

// ---------------------------------------------------------------------------
// GEMM:  C[M,N] = A[M,K] * B[N,K]^T   (both row-major, K contiguous)
// 128x128 block tile, BK=16, 256 threads, 8x8 per-thread microtile.
// ---------------------------------------------------------------------------
#define GBM 128
#define GBN 128
#define GBK 16

__global__ __launch_bounds__(256)
void gemm_nt_kernel(const float* __restrict__ A, const float* __restrict__ B,
                    float* __restrict__ C, int M, int N, int K)
{
    __shared__ float As[GBK][GBM];
    __shared__ float Bs[GBK][GBN];

    const int bm = blockIdx.y * GBM;
    const int bn = blockIdx.x * GBN;
    const int tid = threadIdx.x;
    const int tx = tid & 15;
    const int ty = tid >> 4;

    float acc[8][8];
#pragma unroll
    for (int i = 0; i < 8; i++)
#pragma unroll
        for (int j = 0; j < 8; j++) acc[i][j] = 0.f;

    for (int k0 = 0; k0 < K; k0 += GBK) {
        // load A tile (128x16) transposed into As[k][m]
#pragma unroll
        for (int it = 0; it < 2; it++) {
            int li = tid + it * 256;          // 0..511  (512 float4 = 2048 floats)
            int r  = li >> 2;                 // 0..127
            int c4 = (li & 3) * 4;            // 0,4,8,12
            float4 v = *(const float4*)&A[(size_t)(bm + r) * K + k0 + c4];
            As[c4 + 0][r] = v.x; As[c4 + 1][r] = v.y;
            As[c4 + 2][r] = v.z; As[c4 + 3][r] = v.w;
        }
#pragma unroll
        for (int it = 0; it < 2; it++) {
            int li = tid + it * 256;
            int r  = li >> 2;
            int c4 = (li & 3) * 4;
            float4 v = *(const float4*)&B[(size_t)(bn + r) * K + k0 + c4];
            Bs[c4 + 0][r] = v.x; Bs[c4 + 1][r] = v.y;
            Bs[c4 + 2][r] = v.z; Bs[c4 + 3][r] = v.w;
        }
        __syncthreads();

#pragma unroll
        for (int kk = 0; kk < GBK; kk++) {
            float a[8], b[8];
#pragma unroll
            for (int i = 0; i < 8; i++) a[i] = As[kk][ty * 8 + i];
#pragma unroll
            for (int j = 0; j < 8; j++) b[j] = Bs[kk][tx * 8 + j];
#pragma unroll
            for (int i = 0; i < 8; i++)
#pragma unroll
                for (int j = 0; j < 8; j++)
                    acc[i][j] = fmaf(a[i], b[j], acc[i][j]);
        }
        __syncthreads();
    }

#pragma unroll
    for (int i = 0; i < 8; i++) {
        int r = bm + ty * 8 + i;
#pragma unroll
        for (int j = 0; j < 8; j += 4) {
            float4 v = make_float4(acc[i][j], acc[i][j + 1], acc[i][j + 2], acc[i][j + 3]);
            *(float4*)&C[(size_t)r * N + bn + tx * 8 + j] = v;
        }
    }
}

// ---------------------------------------------------------------------------
// Flash attention with causal mask + GQA.
// Grid: (T/64, H, B), 256 threads. 64x64 S tile, 4x4 per-thread microtile.
// Dynamic smem: Qs(64x65) Ks(64x65) Ps(64x65) Vs(64x64)  fp32
// ---------------------------------------------------------------------------
#define FBM 64
#define FBN 64
#define QS_STRIDE 65
#define FLASH_SMEM_FLOATS (3 * 64 * 65 + 64 * 64)
#define FLASH_SMEM_BYTES  (FLASH_SMEM_FLOATS * 4)

__global__ __launch_bounds__(256)
void flash_attn_kernel()
{
    extern __shared__ float smem[];
    float* Qs = smem;                    // [64][65]
    float* Ks = Qs + 64 * 65;            // [64][65]
    float* Ps = Ks + 64 * 65;            // [64][65]
    float* Vs = Ps + 64 * 65;            // [64][64]  (16B aligned: 3*4160*4 = 49920)

    const int qt  = blockIdx.x;          // query tile (0..31)
    const int h   = blockIdx.y;          // head
    const int b   = blockIdx.z;
    const int kvh = h >> 2;              // h / G

    const int tid = threadIdx.x;
    const int tx  = tid & 15;
    const int ty  = tid >> 4;
    const int qbase = qt * FBM;

    // ---- load Q tile (64 x 64) ----
#pragma unroll
    for (int it = 0; it < 4; it++) {
        int li = tid + it * 256;         // 0..1023 float4 slots
        int r  = li >> 4;                // 0..63
        int c4 = (li & 15) * 4;
        float4 v = *(const float4*)&g_Q[(size_t)(b * TT + qbase + r) * DD + h * HD + c4];
        Qs[r * QS_STRIDE + c4 + 0] = v.x;
        Qs[r * QS_STRIDE + c4 + 1] = v.y;
        Qs[r * QS_STRIDE + c4 + 2] = v.z;
        Qs[r * QS_STRIDE + c4 + 3] = v.w;
    }

    float m_i[4], l_i[4], o[4][4];
#pragma unroll
    for (int i = 0; i < 4; i++) {
        m_i[i] = -1e30f; l_i[i] = 0.f;
#pragma unroll
        for (int j = 0; j < 4; j++) o[i][j] = 0.f;
    }

    const float scale = 0.125f;          // 1/sqrt(64)

    for (int kt = 0; kt <= qt; kt++) {
        const int kbase = kt * FBN;
        // ---- load K,V tiles (64 x 64 each) ----
#pragma unroll
        for (int it = 0; it < 4; it++) {
            int li = tid + it * 256;
            int r  = li >> 4;
            int c4 = (li & 15) * 4;
            size_t goff = (size_t)(b * TT + kbase + r) * DKV + kvh * HD + c4;
            float4 kv = *(const float4*)&g_K[goff];
            Ks[r * QS_STRIDE + c4 + 0] = kv.x;
            Ks[r * QS_STRIDE + c4 + 1] = kv.y;
            Ks[r * QS_STRIDE + c4 + 2] = kv.z;
            Ks[r * QS_STRIDE + c4 + 3] = kv.w;
            float4 vv = *(const float4*)&g_V[goff];
            *(float4*)&Vs[r * 64 + c4] = vv;
        }
        __syncthreads();

        // ---- S = Q K^T (64x64x64) ----
        float s[4][4];
#pragma unroll
        for (int i = 0; i < 4; i++)
#pragma unroll
            for (int j = 0; j < 4; j++) s[i][j] = 0.f;

#pragma unroll 8
        for (int d = 0; d < HD; d++) {
            float a[4], bb[4];
#pragma unroll
            for (int i = 0; i < 4; i++) a[i]  = Qs[(4 * ty + i) * QS_STRIDE + d];
#pragma unroll
            for (int j = 0; j < 4; j++) bb[j] = Ks[(4 * tx + j) * QS_STRIDE + d];
#pragma unroll
            for (int i = 0; i < 4; i++)
#pragma unroll
                for (int j = 0; j < 4; j++)
                    s[i][j] = fmaf(a[i], bb[j], s[i][j]);
        }

        // ---- scale + causal mask ----
        if (kt == qt) {
#pragma unroll
            for (int i = 0; i < 4; i++) {
                int qr = qbase + 4 * ty + i;
#pragma unroll
                for (int j = 0; j < 4; j++) {
                    int kc = kbase + 4 * tx + j;
                    s[i][j] = (kc <= qr) ? s[i][j] * scale : -1e30f;
                }
            }
        } else {
#pragma unroll
            for (int i = 0; i < 4; i++)
#pragma unroll
                for (int j = 0; j < 4; j++) s[i][j] *= scale;
        }

        // ---- online softmax ----
#pragma unroll
        for (int i = 0; i < 4; i++) {
            float rmax = s[i][0];
#pragma unroll
            for (int j = 1; j < 4; j++) rmax = fmaxf(rmax, s[i][j]);
#pragma unroll
            for (int off = 1; off < 16; off <<= 1)
                rmax = fmaxf(rmax, __shfl_xor_sync(0xffffffffu, rmax, off));

            float mn    = fmaxf(m_i[i], rmax);
            float alpha = __expf(m_i[i] - mn);
            m_i[i] = mn;

            float rs = 0.f;
#pragma unroll
            for (int j = 0; j < 4; j++) {
                s[i][j] = __expf(s[i][j] - mn);
                rs += s[i][j];
            }
#pragma unroll
            for (int off = 1; off < 16; off <<= 1)
                rs += __shfl_xor_sync(0xffffffffu, rs, off);

            l_i[i] = l_i[i] * alpha + rs;
#pragma unroll
            for (int j = 0; j < 4; j++) o[i][j] *= alpha;
        }

        // ---- write P to shared, then O += P V ----
#pragma unroll
        for (int i = 0; i < 4; i++)
#pragma unroll
            for (int j = 0; j < 4; j++)
                Ps[(4 * ty + i) * QS_STRIDE + 4 * tx + j] = s[i][j];
        __syncthreads();

#pragma unroll 8
        for (int ss = 0; ss < FBN; ss++) {
            float p[4];
#pragma unroll
            for (int i = 0; i < 4; i++) p[i] = Ps[(4 * ty + i) * QS_STRIDE + ss];
            float4 vv = *(const float4*)&Vs[ss * 64 + 4 * tx];
            float vj[4] = {vv.x, vv.y, vv.z, vv.w};
#pragma unroll
            for (int i = 0; i < 4; i++)
#pragma unroll
                for (int j = 0; j < 4; j++)
                    o[i][j] = fmaf(p[i], vj[j], o[i][j]);
        }
        __syncthreads();
    }

    // ---- epilogue: normalize and store to g_A[b,t, h*64+d] ----
#pragma unroll
    for (int i = 0; i < 4; i++) {
        float inv = 1.f / l_i[i];
        int r = qbase + 4 * ty + i;
#pragma unroll
        for (int j = 0; j < 4; j++)
            g_A[(size_t)(b * TT + r) * DD + h * HD + 4 * tx + j] = o[i][j] * inv;
    }
}

// ---------------------------------------------------------------------------
// Launch
// inputs: 0=x [B,T,D] f32, 1=Wq [D,D], 2=Wk [512,D], 3=Wv [512,D], 4=Wo [D,D],
//         5=mask (ignored; causal computed analytically)
// ---------------------------------------------------------------------------
extern "C" void kernel_launch(void* const* d_in, const int* in_sizes, int n_in,
                              void* d_out, int out_size)
{
    const float* x  = (const float*)d_in[0];
    const float* Wq = (const float*)d_in[1];
    const float* Wk = (const float*)d_in[2];
    const float* Wv = (const float*)d_in[3];
    const float* Wo = (const float*)d_in[4];
    float* out = (float*)d_out;

    float *qp, *kp, *vp, *ap;
    cudaGetSymbolAddress((void**)&qp, g_Q);
    cudaGetSymbolAddress((void**)&kp, g_K);
    cudaGetSymbolAddress((void**)&vp, g_V);
    cudaGetSymbolAddress((void**)&ap, g_A);

    cudaFuncSetAttribute(flash_attn_kernel,
                         cudaFuncAttributeMaxDynamicSharedMemorySize,
                         FLASH_SMEM_BYTES);

    // Projections
    gemm_nt_kernel<<<dim3(DD / GBN, MTOT / GBM), 256>>>(x, Wq, qp, MTOT, DD, DD);
    gemm_nt_kernel<<<dim3(DKV / GBN, MTOT / GBM), 256>>>(x, Wk, kp, MTOT, DKV, DD);
    gemm_nt_kernel<<<dim3(DKV / GBN, MTOT / GBM), 256>>>(x, Wv, vp, MTOT, DKV, DD);

    // Causal GQA flash attention
    flash_attn_kernel<<<dim3(TT / FBM, HH, BB), 256, FLASH_SMEM_BYTES>>>();

    // Output projection
    gemm_nt_kernel<<<dim3(DD / GBN, MTOT / GBM), 256>>>(ap, Wo, out, MTOT, DD, DD);
}

// round 4
// speedup vs baseline: 1.7863x; 1.7863x over previous
#include <cuda_runtime.h>
#include <cuda_bf16.h>
#include <cstdint>
#include <math.h>

// Problem constants
#define BB   2
#define TT   2048
#define DD   2048
#define HH   32
#define KVH  8
#define HD   64
#define MTOT (BB*TT)      // 4096
#define DKV  (KVH*HD)     // 512

// ---------------------------------------------------------------------------
// Scratch (__device__ globals; no allocation allowed)
// ---------------------------------------------------------------------------
__device__ float g_Q[(size_t)MTOT * DD];
__device__ float g_K[(size_t)MTOT * DKV];
__device__ float g_V[(size_t)MTOT * DKV];
__device__ float g_A[(size_t)MTOT * DD];

__device__ __nv_bfloat16 g_xhi[(size_t)MTOT * DD],  g_xlo[(size_t)MTOT * DD];
__device__ __nv_bfloat16 g_Wqhi[(size_t)DD * DD],   g_Wqlo[(size_t)DD * DD];
__device__ __nv_bfloat16 g_Wkhi[(size_t)DKV * DD],  g_Wklo[(size_t)DKV * DD];
__device__ __nv_bfloat16 g_Wvhi[(size_t)DKV * DD],  g_Wvlo[(size_t)DKV * DD];
__device__ __nv_bfloat16 g_Wohi[(size_t)DD * DD],   g_Wolo[(size_t)DD * DD];
__device__ __nv_bfloat16 g_Ahi[(size_t)MTOT * DD],  g_Alo[(size_t)MTOT * DD];

// ---------------------------------------------------------------------------
// Helpers (portable PTX only: cp.async / ldmatrix / mma.sync)
// ---------------------------------------------------------------------------
__device__ __forceinline__ uint32_t s2u(const void* p) {
    return (uint32_t)__cvta_generic_to_shared(p);
}

#define CP16(sa, ga) \
    asm volatile("cp.async.cg.shared.global [%0], [%1], 16;" :: "r"(sa), "l"(ga) : "memory")
#define CPCOMMIT()  asm volatile("cp.async.commit_group;" ::: "memory")
#define CPWAIT(n)   asm volatile("cp.async.wait_group %0;" :: "n"(n) : "memory")

#define LDSM4(r0, r1, r2, r3, addr) \
    asm volatile("ldmatrix.sync.aligned.m8n8.x4.shared.b16 {%0,%1,%2,%3}, [%4];" \
        : "=r"(r0), "=r"(r1), "=r"(r2), "=r"(r3) : "r"(addr))

#define MMA16816(d, a, b) \
    asm volatile("mma.sync.aligned.m16n8k16.row.col.f32.bf16.bf16.f32 " \
        "{%0,%1,%2,%3}, {%4,%5,%6,%7}, {%8,%9}, {%0,%1,%2,%3};" \
        : "+f"((d)[0]), "+f"((d)[1]), "+f"((d)[2]), "+f"((d)[3]) \
        : "r"((a)[0]), "r"((a)[1]), "r"((a)[2]), "r"((a)[3]), "r"((b)[0]), "r"((b)[1]))

// Swizzled smem address: tile rows are 64B (32 bf16); 16B chunk c XORed by row
// bits to make ldmatrix (8 rows x 16B) conflict-free.
__device__ __forceinline__ uint32_t sw_addr(uint32_t base, int row, int chunk) {
    return base + row * 64 + ((chunk ^ ((row >> 1) & 3)) << 4);
}

// ---------------------------------------------------------------------------
// fp32 -> (bf16 hi, bf16 lo) split kernel (vectorized by 4)
// ---------------------------------------------------------------------------
__global__ __launch_bounds__(256)
void split_kernel(const float* __restrict__ src, __nv_bfloat16* __restrict__ hi,
                  __nv_bfloat16* __restrict__ lo, int n4)
{
    int i = blockIdx.x * blockDim.x + threadIdx.x;
    if (i >= n4) return;
    float4 v = ((const float4*)src)[i];
    __nv_bfloat16 h0 = __float2bfloat16(v.x);
    __nv_bfloat16 h1 = __float2bfloat16(v.y);
    __nv_bfloat16 h2 = __float2bfloat16(v.z);
    __nv_bfloat16 h3 = __float2bfloat16(v.w);
    __nv_bfloat16 l0 = __float2bfloat16(v.x - __bfloat162float(h0));
    __nv_bfloat16 l1 = __float2bfloat16(v.y - __bfloat162float(h1));
    __nv_bfloat16 l2 = __float2bfloat16(v.z - __bfloat162float(h2));
    __nv_bfloat16 l3 = __float2bfloat16(v.w - __bfloat162float(h3));
    __nv_bfloat162 hp0 = __nv_bfloat162(h0, h1), hp1 = __nv_bfloat162(h2, h3);
    __nv_bfloat162 lp0 = __nv_bfloat162(l0, l1), lp1 = __nv_bfloat162(l2, l3);
    uint2 hv, lv;
    hv.x = *(uint32_t*)&hp0; hv.y = *(uint32_t*)&hp1;
    lv.x = *(uint32_t*)&lp0; lv.y = *(uint32_t*)&lp1;
    ((uint2*)hi)[i] = hv;
    ((uint2*)lo)[i] = lv;
}

// ---------------------------------------------------------------------------
// mma.sync GEMM:  C[M,N] = A[M,K] * B[N,K]^T  (3-pass bf16 split precision)
// CTA 128x128, BK=32, 3-stage cp.async pipeline, 8 warps (2x4), warp tile 64x32.
// Stage = 4 tiles (Ahi,Alo,Bhi,Blo) of 128x32 bf16 = 8KB each -> 32KB/stage.
// ---------------------------------------------------------------------------
#define STAGES      3
#define TILE_B      8192          // 128 rows * 64 bytes
#define STAGE_B     (4 * TILE_B)  // 32768
#define GEMM_SMEM   (STAGES * STAGE_B)

__global__ __launch_bounds__(256)
void gemm_tc_kernel(const __nv_bfloat16* __restrict__ Ahi, const __nv_bfloat16* __restrict__ Alo,
                    const __nv_bfloat16* __restrict__ Bhi, const __nv_bfloat16* __restrict__ Blo,
                    float* __restrict__ C, int M, int N, int K)
{
    extern __shared__ __align__(128) char smem[];
    const uint32_t sbase = s2u(smem);

    const int tid = threadIdx.x;
    const int wid = tid >> 5;
    const int lane = tid & 31;
    const int bm = blockIdx.y * 128;
    const int bn = blockIdx.x * 128;

    const int wm = (wid & 1) * 64;   // warp M offset within CTA tile
    const int wn = (wid >> 1) * 32;  // warp N offset

    const char* srcs[4] = {(const char*)Ahi, (const char*)Alo,
                           (const char*)Bhi, (const char*)Blo};
    const size_t rowstride = (size_t)K * 2;

    const int NC = K >> 5;           // K / 32

    // ---- stage loader: chunk c -> stage s ----
    auto load_chunk = [&](int c, int s) {
        const uint32_t sb = sbase + s * STAGE_B;
        const size_t k0b = (size_t)c * 64;   // 32 bf16 = 64 bytes
#pragma unroll
        for (int t = 0; t < 4; t++) {
            const int rbase = (t < 2) ? bm : bn;
            const char* src = srcs[t];
#pragma unroll
            for (int j = 0; j < 2; j++) {
                int i = tid + j * 256;       // 0..511
                int r = i >> 2;              // row 0..127
                int ck = i & 3;              // 16B chunk
                const char* ga = src + (size_t)(rbase + r) * rowstride + k0b + ck * 16;
                CP16(sw_addr(sb + t * TILE_B, r, ck), ga);
            }
        }
    };

    float acc[4][4][4];              // [fm][fn][4]
#pragma unroll
    for (int i = 0; i < 4; i++)
#pragma unroll
        for (int j = 0; j < 4; j++)
#pragma unroll
            for (int q = 0; q < 4; q++) acc[i][j][q] = 0.f;

    // prologue: stages 0,1
    load_chunk(0, 0); CPCOMMIT();
    load_chunk(1, 1); CPCOMMIT();

    for (int c = 0; c < NC; c++) {
        const int s = c % STAGES;
        CPWAIT(1);
        __syncthreads();

        if (c + 2 < NC) load_chunk(c + 2, (c + 2) % STAGES);
        CPCOMMIT();

        const uint32_t sb   = sbase + s * STAGE_B;
        const uint32_t sAhi = sb;
        const uint32_t sAlo = sb + TILE_B;
        const uint32_t sBhi = sb + 2 * TILE_B;
        const uint32_t sBlo = sb + 3 * TILE_B;

#pragma unroll
        for (int ks = 0; ks < 2; ks++) {       // two k16 steps per BK=32
            const int ckbase = ks * 2;         // 16B chunk index of k-step

            // ---- load fragments ----
            uint32_t ahi[4][4], alo[4][4], bhi[4][2], blo[4][2];
            {
                // A: row = wm + fm*16 + (lane&15), chunk = ckbase + (lane>>4)
                int ar = (lane & 15);
                int ac = ckbase + (lane >> 4);
#pragma unroll
                for (int fm = 0; fm < 4; fm++) {
                    uint32_t ad = sw_addr(sAhi, wm + fm * 16 + ar, ac);
                    LDSM4(ahi[fm][0], ahi[fm][1], ahi[fm][2], ahi[fm][3], ad);
                    uint32_t ad2 = sw_addr(sAlo, wm + fm * 16 + ar, ac);
                    LDSM4(alo[fm][0], alo[fm][1], alo[fm][2], alo[fm][3], ad2);
                }
                // B: covers 2 n8-frags per ldmatrix.x4
                int br = (lane & 7);
                int bsel = (lane >> 4);          // which of the 2 frags
                int bc = ckbase + ((lane >> 3) & 1);
#pragma unroll
                for (int fp = 0; fp < 2; fp++) {
                    uint32_t bd = sw_addr(sBhi, wn + (fp * 2 + bsel) * 8 + br, bc);
                    uint32_t t0, t1, t2, t3;
                    LDSM4(t0, t1, t2, t3, bd);
                    bhi[fp * 2][0] = t0; bhi[fp * 2][1] = t1;
                    bhi[fp * 2 + 1][0] = t2; bhi[fp * 2 + 1][1] = t3;
                    uint32_t bd2 = sw_addr(sBlo, wn + (fp * 2 + bsel) * 8 + br, bc);
                    LDSM4(t0, t1, t2, t3, bd2);
                    blo[fp * 2][0] = t0; blo[fp * 2][1] = t1;
                    blo[fp * 2 + 1][0] = t2; blo[fp * 2 + 1][1] = t3;
                }
            }

            // ---- 3-pass MMA ----
#pragma unroll
            for (int fm = 0; fm < 4; fm++)
#pragma unroll
                for (int fn = 0; fn < 4; fn++) {
                    MMA16816(acc[fm][fn], ahi[fm], bhi[fn]);
                    MMA16816(acc[fm][fn], alo[fm], bhi[fn]);
                    MMA16816(acc[fm][fn], ahi[fm], blo[fn]);
                }
        }
        __syncthreads();
    }

    // ---- epilogue ----
    const int lr = lane >> 2;        // 0..7
    const int lc = (lane & 3) * 2;   // 0,2,4,6
#pragma unroll
    for (int fm = 0; fm < 4; fm++) {
#pragma unroll
        for (int fn = 0; fn < 4; fn++) {
            int r0 = bm + wm + fm * 16 + lr;
            int cc = bn + wn + fn * 8 + lc;
            *(float2*)&C[(size_t)r0 * N + cc]       = make_float2(acc[fm][fn][0], acc[fm][fn][1]);
            *(float2*)&C[(size_t)(r0 + 8) * N + cc] = make_float2(acc[fm][fn][2], acc[fm][fn][3]);
        }
    }
}

// ---------------------------------------------------------------------------
// Flash attention (SIMT fp32) — unchanged from R1 (passing)
// ---------------------------------------------------------------------------
#define FBM 64
#define FBN 64
#define QS_STRIDE 65
#define FLASH_SMEM_FLOATS (3 * 64 * 65 + 64 * 64)
#define FLASH_SMEM_BYTES  (FLASH_SMEM_FLOATS * 4)

__global__ __launch_bounds__(256)
void flash_attn_kernel()
{
    extern __shared__ float fsmem[];
    float* Qs = fsmem;
    float* Ks = Qs + 64 * 65;
    float* Ps = Ks + 64 * 65;
    float* Vs = Ps + 64 * 65;

    const int qt  = blockIdx.x;
    const int h   = blockIdx.y;
    const int b   = blockIdx.z;
    const int kvh = h >> 2;

    const int tid = threadIdx.x;
    const int tx  = tid & 15;
    const int ty  = tid >> 4;
    const int qbase = qt * FBM;

#pragma unroll
    for (int it = 0; it < 4; it++) {
        int li = tid + it * 256;
        int r  = li >> 4;
        int c4 = (li & 15) * 4;
        float4 v = *(const float4*)&g_Q[(size_t)(b * TT + qbase + r) * DD + h * HD + c4];
        Qs[r * QS_STRIDE + c4 + 0] = v.x;
        Qs[r * QS_STRIDE + c4 + 1] = v.y;
        Qs[r * QS_STRIDE + c4 + 2] = v.z;
        Qs[r * QS_STRIDE + c4 + 3] = v.w;
    }

    float m_i[4], l_i[4], o[4][4];
#pragma unroll
    for (int i = 0; i < 4; i++) {
        m_i[i] = -1e30f; l_i[i] = 0.f;
#pragma unroll
        for (int j = 0; j < 4; j++) o[i][j] = 0.f;
    }

    const float scale = 0.125f;

    for (int kt = 0; kt <= qt; kt++) {
        const int kbase = kt * FBN;
#pragma unroll
        for (int it = 0; it < 4; it++) {
            int li = tid + it * 256;
            int r  = li >> 4;
            int c4 = (li & 15) * 4;
            size_t goff = (size_t)(b * TT + kbase + r) * DKV + kvh * HD + c4;
            float4 kv = *(const float4*)&g_K[goff];
            Ks[r * QS_STRIDE + c4 + 0] = kv.x;
            Ks[r * QS_STRIDE + c4 + 1] = kv.y;
            Ks[r * QS_STRIDE + c4 + 2] = kv.z;
            Ks[r * QS_STRIDE + c4 + 3] = kv.w;
            float4 vv = *(const float4*)&g_V[goff];
            *(float4*)&Vs[r * 64 + c4] = vv;
        }
        __syncthreads();

        float s[4][4];
#pragma unroll
        for (int i = 0; i < 4; i++)
#pragma unroll
            for (int j = 0; j < 4; j++) s[i][j] = 0.f;

#pragma unroll 8
        for (int d = 0; d < HD; d++) {
            float a[4], bb[4];
#pragma unroll
            for (int i = 0; i < 4; i++) a[i]  = Qs[(4 * ty + i) * QS_STRIDE + d];
#pragma unroll
            for (int j = 0; j < 4; j++) bb[j] = Ks[(4 * tx + j) * QS_STRIDE + d];
#pragma unroll
            for (int i = 0; i < 4; i++)
#pragma unroll
                for (int j = 0; j < 4; j++)
                    s[i][j] = fmaf(a[i], bb[j], s[i][j]);
        }

        if (kt == qt) {
#pragma unroll
            for (int i = 0; i < 4; i++) {
                int qr = qbase + 4 * ty + i;
#pragma unroll
                for (int j = 0; j < 4; j++) {
                    int kc = kbase + 4 * tx + j;
                    s[i][j] = (kc <= qr) ? s[i][j] * scale : -1e30f;
                }
            }
        } else {
#pragma unroll
            for (int i = 0; i < 4; i++)
#pragma unroll
                for (int j = 0; j < 4; j++) s[i][j] *= scale;
        }

#pragma unroll
        for (int i = 0; i < 4; i++) {
            float rmax = s[i][0];
#pragma unroll
            for (int j = 1; j < 4; j++) rmax = fmaxf(rmax, s[i][j]);
#pragma unroll
            for (int off = 1; off < 16; off <<= 1)
                rmax = fmaxf(rmax, __shfl_xor_sync(0xffffffffu, rmax, off));

            float mn    = fmaxf(m_i[i], rmax);
            float alpha = __expf(m_i[i] - mn);
            m_i[i] = mn;

            float rs = 0.f;
#pragma unroll
            for (int j = 0; j < 4; j++) {
                s[i][j] = __expf(s[i][j] - mn);
                rs += s[i][j];
            }
#pragma unroll
            for (int off = 1; off < 16; off <<= 1)
                rs += __shfl_xor_sync(0xffffffffu, rs, off);

            l_i[i] = l_i[i] * alpha + rs;
#pragma unroll
            for (int j = 0; j < 4; j++) o[i][j] *= alpha;
        }

#pragma unroll
        for (int i = 0; i < 4; i++)
#pragma unroll
            for (int j = 0; j < 4; j++)
                Ps[(4 * ty + i) * QS_STRIDE + 4 * tx + j] = s[i][j];
        __syncthreads();

#pragma unroll 8
        for (int ss = 0; ss < FBN; ss++) {
            float p[4];
#pragma unroll
            for (int i = 0; i < 4; i++) p[i] = Ps[(4 * ty + i) * QS_STRIDE + ss];
            float4 vv = *(const float4*)&Vs[ss * 64 + 4 * tx];
            float vj[4] = {vv.x, vv.y, vv.z, vv.w};
#pragma unroll
            for (int i = 0; i < 4; i++)
#pragma unroll
                for (int j = 0; j < 4; j++)
                    o[i][j] = fmaf(p[i], vj[j], o[i][j]);
        }
        __syncthreads();
    }

#pragma unroll
    for (int i = 0; i < 4; i++) {
        float inv = 1.f / l_i[i];
        int r = qbase + 4 * ty + i;
#pragma unroll
        for (int j = 0; j < 4; j++)
            g_A[(size_t)(b * TT + r) * DD + h * HD + 4 * tx + j] = o[i][j] * inv;
    }
}

// ---------------------------------------------------------------------------
// Launch
// ---------------------------------------------------------------------------
extern "C" void kernel_launch(void* const* d_in, const int* in_sizes, int n_in,
                              void* d_out, int out_size)
{
    const float* x  = (const float*)d_in[0];
    const float* Wq = (const float*)d_in[1];
    const float* Wk = (const float*)d_in[2];
    const float* Wv = (const float*)d_in[3];
    const float* Wo = (const float*)d_in[4];
    float* out = (float*)d_out;

    float *qp, *kp, *vp, *ap;
    __nv_bfloat16 *xh, *xl, *wqh, *wql, *wkh, *wkl, *wvh, *wvl, *woh, *wol, *ah, *al;
    cudaGetSymbolAddress((void**)&qp, g_Q);
    cudaGetSymbolAddress((void**)&kp, g_K);
    cudaGetSymbolAddress((void**)&vp, g_V);
    cudaGetSymbolAddress((void**)&ap, g_A);
    cudaGetSymbolAddress((void**)&xh, g_xhi);   cudaGetSymbolAddress((void**)&xl, g_xlo);
    cudaGetSymbolAddress((void**)&wqh, g_Wqhi); cudaGetSymbolAddress((void**)&wql, g_Wqlo);
    cudaGetSymbolAddress((void**)&wkh, g_Wkhi); cudaGetSymbolAddress((void**)&wkl, g_Wklo);
    cudaGetSymbolAddress((void**)&wvh, g_Wvhi); cudaGetSymbolAddress((void**)&wvl, g_Wvlo);
    cudaGetSymbolAddress((void**)&woh, g_Wohi); cudaGetSymbolAddress((void**)&wol, g_Wolo);
    cudaGetSymbolAddress((void**)&ah, g_Ahi);   cudaGetSymbolAddress((void**)&al, g_Alo);

    cudaFuncSetAttribute(gemm_tc_kernel,
                         cudaFuncAttributeMaxDynamicSharedMemorySize, GEMM_SMEM);
    cudaFuncSetAttribute(flash_attn_kernel,
                         cudaFuncAttributeMaxDynamicSharedMemorySize, FLASH_SMEM_BYTES);

    // fp32 -> bf16 hi/lo splits
    const int n_x  = MTOT * DD / 4, n_wq = DD * DD / 4, n_wk = DKV * DD / 4;
    split_kernel<<<(n_x  + 255) / 256, 256>>>(x,  xh,  xl,  n_x);
    split_kernel<<<(n_wq + 255) / 256, 256>>>(Wq, wqh, wql, n_wq);
    split_kernel<<<(n_wk + 255) / 256, 256>>>(Wk, wkh, wkl, n_wk);
    split_kernel<<<(n_wk + 255) / 256, 256>>>(Wv, wvh, wvl, n_wk);
    split_kernel<<<(n_wq + 255) / 256, 256>>>(Wo, woh, wol, n_wq);

    // Projections (tensor core via mma.sync)
    gemm_tc_kernel<<<dim3(DD / 128, MTOT / 128), 256, GEMM_SMEM>>>(xh, xl, wqh, wql, qp, MTOT, DD, DD);
    gemm_tc_kernel<<<dim3(DKV / 128, MTOT / 128), 256, GEMM_SMEM>>>(xh, xl, wkh, wkl, kp, MTOT, DKV, DD);
    gemm_tc_kernel<<<dim3(DKV / 128, MTOT / 128), 256, GEMM_SMEM>>>(xh, xl, wvh, wvl, vp, MTOT, DKV, DD);

    // Causal GQA flash attention (fp32 SIMT)
    flash_attn_kernel<<<dim3(TT / FBM, HH, BB), 256, FLASH_SMEM_BYTES>>>();

    // Split attention output, then output projection (tensor core)
    split_kernel<<<(n_x + 255) / 256, 256>>>(ap, ah, al, n_x);
    gemm_tc_kernel<<<dim3(DD / 128, MTOT / 128), 256, GEMM_SMEM>>>(ah, al, woh, wol, out, MTOT, DD, DD);
}

// round 5
// speedup vs baseline: 3.0653x; 1.7161x over previous
#include <cuda_runtime.h>
#include <cuda_bf16.h>
#include <cstdint>
#include <math.h>

// Problem constants
#define BB   2
#define TT   2048
#define DD   2048
#define HH   32
#define KVH  8
#define HD   64
#define MTOT (BB*TT)      // 4096
#define DKV  (KVH*HD)     // 512

// ---------------------------------------------------------------------------
// Scratch (__device__ globals; no allocation allowed) — all split bf16 pairs
// ---------------------------------------------------------------------------
__device__ __nv_bfloat16 g_xhi[(size_t)MTOT * DD],  g_xlo[(size_t)MTOT * DD];
__device__ __nv_bfloat16 g_Wqhi[(size_t)DD * DD],   g_Wqlo[(size_t)DD * DD];
__device__ __nv_bfloat16 g_Wkhi[(size_t)DKV * DD],  g_Wklo[(size_t)DKV * DD];
__device__ __nv_bfloat16 g_Wvhi[(size_t)DKV * DD],  g_Wvlo[(size_t)DKV * DD];
__device__ __nv_bfloat16 g_Wohi[(size_t)DD * DD],   g_Wolo[(size_t)DD * DD];

__device__ __nv_bfloat16 g_Qhi[(size_t)MTOT * DD],  g_Qlo[(size_t)MTOT * DD];
__device__ __nv_bfloat16 g_Khi[(size_t)MTOT * DKV], g_Klo[(size_t)MTOT * DKV];
__device__ __nv_bfloat16 g_Vhi[(size_t)MTOT * DKV], g_Vlo[(size_t)MTOT * DKV];
__device__ __nv_bfloat16 g_Ahi[(size_t)MTOT * DD],  g_Alo[(size_t)MTOT * DD];

// ---------------------------------------------------------------------------
// Helpers (portable PTX only: cp.async / ldmatrix / mma.sync)
// ---------------------------------------------------------------------------
__device__ __forceinline__ uint32_t s2u(const void* p) {
    return (uint32_t)__cvta_generic_to_shared(p);
}

#define CP16(sa, ga) \
    asm volatile("cp.async.cg.shared.global [%0], [%1], 16;" :: "r"(sa), "l"(ga) : "memory")
#define CPCOMMIT()  asm volatile("cp.async.commit_group;" ::: "memory")
#define CPWAIT(n)   asm volatile("cp.async.wait_group %0;" :: "n"(n) : "memory")

#define LDSM4(r0, r1, r2, r3, addr) \
    asm volatile("ldmatrix.sync.aligned.m8n8.x4.shared.b16 {%0,%1,%2,%3}, [%4];" \
        : "=r"(r0), "=r"(r1), "=r"(r2), "=r"(r3) : "r"(addr))

#define LDSM4T(r0, r1, r2, r3, addr) \
    asm volatile("ldmatrix.sync.aligned.m8n8.x4.trans.shared.b16 {%0,%1,%2,%3}, [%4];" \
        : "=r"(r0), "=r"(r1), "=r"(r2), "=r"(r3) : "r"(addr))

#define MMA16816(d, a, b) \
    asm volatile("mma.sync.aligned.m16n8k16.row.col.f32.bf16.bf16.f32 " \
        "{%0,%1,%2,%3}, {%4,%5,%6,%7}, {%8,%9}, {%0,%1,%2,%3};" \
        : "+f"((d)[0]), "+f"((d)[1]), "+f"((d)[2]), "+f"((d)[3]) \
        : "r"((a)[0]), "r"((a)[1]), "r"((a)[2]), "r"((a)[3]), "r"((b)[0]), "r"((b)[1]))

#define MMA16816R(d, a, b0v, b1v) \
    asm volatile("mma.sync.aligned.m16n8k16.row.col.f32.bf16.bf16.f32 " \
        "{%0,%1,%2,%3}, {%4,%5,%6,%7}, {%8,%9}, {%0,%1,%2,%3};" \
        : "+f"((d)[0]), "+f"((d)[1]), "+f"((d)[2]), "+f"((d)[3]) \
        : "r"((a)[0]), "r"((a)[1]), "r"((a)[2]), "r"((a)[3]), "r"(b0v), "r"(b1v))

// 64B-row swizzle (GEMM tiles): 16B chunk XORed by row bits
__device__ __forceinline__ uint32_t sw_addr(uint32_t base, int row, int chunk) {
    return base + row * 64 + ((chunk ^ ((row >> 1) & 3)) << 4);
}
// 128B-row swizzle (flash tiles)
__device__ __forceinline__ uint32_t sw128(uint32_t base, int row, int chunk) {
    return base + row * 128 + ((chunk ^ (row & 7)) << 4);
}

// split fp32 pair -> packed bf16x2 (hi, lo arrays). x0 = even col (low half).
__device__ __forceinline__ void pack_split(float x0, float x1, uint32_t& hi, uint32_t& lo) {
    __nv_bfloat16 h0 = __float2bfloat16(x0);
    __nv_bfloat16 h1 = __float2bfloat16(x1);
    __nv_bfloat16 l0 = __float2bfloat16(x0 - __bfloat162float(h0));
    __nv_bfloat16 l1 = __float2bfloat16(x1 - __bfloat162float(h1));
    __nv_bfloat162 hp(h0, h1), lp(l0, l1);
    hi = *(uint32_t*)&hp;
    lo = *(uint32_t*)&lp;
}

// ---------------------------------------------------------------------------
// fp32 -> (bf16 hi, bf16 lo) split kernel (inputs only)
// ---------------------------------------------------------------------------
__global__ __launch_bounds__(256)
void split_kernel(const float* __restrict__ src, __nv_bfloat16* __restrict__ hi,
                  __nv_bfloat16* __restrict__ lo, int n4)
{
    int i = blockIdx.x * blockDim.x + threadIdx.x;
    if (i >= n4) return;
    float4 v = ((const float4*)src)[i];
    uint32_t h0, l0, h1, l1;
    pack_split(v.x, v.y, h0, l0);
    pack_split(v.z, v.w, h1, l1);
    uint2 hv = make_uint2(h0, h1), lv = make_uint2(l0, l1);
    ((uint2*)hi)[i] = hv;
    ((uint2*)lo)[i] = lv;
}

// ---------------------------------------------------------------------------
// mma.sync GEMM:  C = A * B^T  (3-pass bf16 split precision)
// CTA 128x128, BK=32, 3-stage cp.async, 8 warps (2x4), warp tile 64x32.
// SPLIT=true: write bf16 (hi,lo) pair outputs; else fp32.
// ---------------------------------------------------------------------------
#define STAGES      3
#define TILE_B      8192
#define STAGE_B     (4 * TILE_B)
#define GEMM_SMEM   (STAGES * STAGE_B)

template<bool SPLIT>
__global__ __launch_bounds__(256)
void gemm_tc_kernel(const __nv_bfloat16* __restrict__ Ahi, const __nv_bfloat16* __restrict__ Alo,
                    const __nv_bfloat16* __restrict__ Bhi, const __nv_bfloat16* __restrict__ Blo,
                    float* __restrict__ C,
                    __nv_bfloat16* __restrict__ Chi, __nv_bfloat16* __restrict__ Clo,
                    int M, int N, int K)
{
    extern __shared__ __align__(128) char smem[];
    const uint32_t sbase = s2u(smem);

    const int tid = threadIdx.x;
    const int wid = tid >> 5;
    const int lane = tid & 31;
    const int bm = blockIdx.y * 128;
    const int bn = blockIdx.x * 128;

    const int wm = (wid & 1) * 64;
    const int wn = (wid >> 1) * 32;

    const char* srcs[4] = {(const char*)Ahi, (const char*)Alo,
                           (const char*)Bhi, (const char*)Blo};
    const size_t rowstride = (size_t)K * 2;

    const int NC = K >> 5;

    auto load_chunk = [&](int c, int s) {
        const uint32_t sb = sbase + s * STAGE_B;
        const size_t k0b = (size_t)c * 64;
#pragma unroll
        for (int t = 0; t < 4; t++) {
            const int rbase = (t < 2) ? bm : bn;
            const char* src = srcs[t];
#pragma unroll
            for (int j = 0; j < 2; j++) {
                int i = tid + j * 256;
                int r = i >> 2;
                int ck = i & 3;
                const char* ga = src + (size_t)(rbase + r) * rowstride + k0b + ck * 16;
                CP16(sw_addr(sb + t * TILE_B, r, ck), ga);
            }
        }
    };

    float acc[4][4][4];
#pragma unroll
    for (int i = 0; i < 4; i++)
#pragma unroll
        for (int j = 0; j < 4; j++)
#pragma unroll
            for (int q = 0; q < 4; q++) acc[i][j][q] = 0.f;

    load_chunk(0, 0); CPCOMMIT();
    load_chunk(1, 1); CPCOMMIT();

    for (int c = 0; c < NC; c++) {
        const int s = c % STAGES;
        CPWAIT(1);
        __syncthreads();

        if (c + 2 < NC) load_chunk(c + 2, (c + 2) % STAGES);
        CPCOMMIT();

        const uint32_t sb   = sbase + s * STAGE_B;
        const uint32_t sAhi = sb;
        const uint32_t sAlo = sb + TILE_B;
        const uint32_t sBhi = sb + 2 * TILE_B;
        const uint32_t sBlo = sb + 3 * TILE_B;

#pragma unroll
        for (int ks = 0; ks < 2; ks++) {
            const int ckbase = ks * 2;

            uint32_t ahi[4][4], alo[4][4], bhi[4][2], blo[4][2];
            {
                int ar = (lane & 15);
                int ac = ckbase + (lane >> 4);
#pragma unroll
                for (int fm = 0; fm < 4; fm++) {
                    uint32_t ad = sw_addr(sAhi, wm + fm * 16 + ar, ac);
                    LDSM4(ahi[fm][0], ahi[fm][1], ahi[fm][2], ahi[fm][3], ad);
                    uint32_t ad2 = sw_addr(sAlo, wm + fm * 16 + ar, ac);
                    LDSM4(alo[fm][0], alo[fm][1], alo[fm][2], alo[fm][3], ad2);
                }
                int br = (lane & 7);
                int bsel = (lane >> 4);
                int bc = ckbase + ((lane >> 3) & 1);
#pragma unroll
                for (int fp = 0; fp < 2; fp++) {
                    uint32_t bd = sw_addr(sBhi, wn + (fp * 2 + bsel) * 8 + br, bc);
                    uint32_t t0, t1, t2, t3;
                    LDSM4(t0, t1, t2, t3, bd);
                    bhi[fp * 2][0] = t0; bhi[fp * 2][1] = t1;
                    bhi[fp * 2 + 1][0] = t2; bhi[fp * 2 + 1][1] = t3;
                    uint32_t bd2 = sw_addr(sBlo, wn + (fp * 2 + bsel) * 8 + br, bc);
                    LDSM4(t0, t1, t2, t3, bd2);
                    blo[fp * 2][0] = t0; blo[fp * 2][1] = t1;
                    blo[fp * 2 + 1][0] = t2; blo[fp * 2 + 1][1] = t3;
                }
            }

#pragma unroll
            for (int fm = 0; fm < 4; fm++)
#pragma unroll
                for (int fn = 0; fn < 4; fn++) {
                    MMA16816(acc[fm][fn], ahi[fm], bhi[fn]);
                    MMA16816(acc[fm][fn], alo[fm], bhi[fn]);
                    MMA16816(acc[fm][fn], ahi[fm], blo[fn]);
                }
        }
        __syncthreads();
    }

    const int lr = lane >> 2;
    const int lc = (lane & 3) * 2;
#pragma unroll
    for (int fm = 0; fm < 4; fm++) {
#pragma unroll
        for (int fn = 0; fn < 4; fn++) {
            int r0 = bm + wm + fm * 16 + lr;
            int cc = bn + wn + fn * 8 + lc;
            if (SPLIT) {
                uint32_t h, l;
                pack_split(acc[fm][fn][0], acc[fm][fn][1], h, l);
                *(uint32_t*)&Chi[(size_t)r0 * N + cc] = h;
                *(uint32_t*)&Clo[(size_t)r0 * N + cc] = l;
                pack_split(acc[fm][fn][2], acc[fm][fn][3], h, l);
                *(uint32_t*)&Chi[(size_t)(r0 + 8) * N + cc] = h;
                *(uint32_t*)&Clo[(size_t)(r0 + 8) * N + cc] = l;
            } else {
                *(float2*)&C[(size_t)r0 * N + cc]       = make_float2(acc[fm][fn][0], acc[fm][fn][1]);
                *(float2*)&C[(size_t)(r0 + 8) * N + cc] = make_float2(acc[fm][fn][2], acc[fm][fn][3]);
            }
        }
    }
}

// ---------------------------------------------------------------------------
// Tensor-core flash attention (split-precision bf16 mma).
// Grid (T/128, H, B), 256 threads = 8 warps x 16 q-rows.
// KV tile 64. Double-buffered cp.async stages (Khi,Klo,Vhi,Vlo @ 8KB each).
// SMEM: Qhi(16K) Qlo(16K) + 2 stages x 32K = 96KB.
// ---------------------------------------------------------------------------
#define QTILE_B   16384
#define KVSUB_B   8192
#define FSTAGE_B  (4 * KVSUB_B)
#define FLASH_SMEM (2 * QTILE_B + 2 * FSTAGE_B)

__global__ __launch_bounds__(256, 1)
void flash_tc_kernel()
{
    extern __shared__ __align__(128) char fsm[];
    const uint32_t sbase = s2u(fsm);
    const uint32_t QHI = sbase;
    const uint32_t QLO = sbase + QTILE_B;
    const uint32_t STG0 = sbase + 2 * QTILE_B;

    const int qt  = blockIdx.x;
    const int h   = blockIdx.y;
    const int b   = blockIdx.z;
    const int kvh = h >> 2;
    const int qb  = qt * 128;

    const int tid = threadIdx.x;
    const int wid = tid >> 5;
    const int lane = tid & 31;

    // ---- load Q tile (hi/lo), 128 rows x 128B each ----
#pragma unroll
    for (int j = 0; j < 4; j++) {
        int i = tid + j * 256;           // 0..1023
        int r = i >> 3;
        int ck = i & 7;
        size_t e = (size_t)(b * TT + qb + r) * DD + h * HD + ck * 8;
        CP16(sw128(QHI, r, ck), (const char*)&g_Qhi[e]);
        CP16(sw128(QLO, r, ck), (const char*)&g_Qlo[e]);
    }
    CPCOMMIT();

    auto load_kv = [&](int kt, int s) {
        const uint32_t sb = STG0 + s * FSTAGE_B;
#pragma unroll
        for (int j = 0; j < 2; j++) {
            int i = tid + j * 256;       // 0..511
            int r = i >> 3;
            int ck = i & 7;
            size_t e = (size_t)(b * TT + kt * 64 + r) * DKV + kvh * HD + ck * 8;
            uint32_t so = sw128(sb, r, ck);
            CP16(so,               (const char*)&g_Khi[e]);
            CP16(so + KVSUB_B,     (const char*)&g_Klo[e]);
            CP16(so + 2 * KVSUB_B, (const char*)&g_Vhi[e]);
            CP16(so + 3 * KVSUB_B, (const char*)&g_Vlo[e]);
        }
    };

    load_kv(0, 0);
    CPCOMMIT();
    CPWAIT(0);
    __syncthreads();

    // ---- extract Q fragments (register-resident for whole loop) ----
    uint32_t qhiF[4][4], qloF[4][4];
    {
        int ar = lane & 15;
        int ac = lane >> 4;
#pragma unroll
        for (int ks = 0; ks < 4; ks++) {
            uint32_t ad = sw128(QHI, wid * 16 + ar, 2 * ks + ac);
            LDSM4(qhiF[ks][0], qhiF[ks][1], qhiF[ks][2], qhiF[ks][3], ad);
            uint32_t ad2 = sw128(QLO, wid * 16 + ar, 2 * ks + ac);
            LDSM4(qloF[ks][0], qloF[ks][1], qloF[ks][2], qloF[ks][3], ad2);
        }
    }

    float oacc[8][4];
#pragma unroll
    for (int i = 0; i < 8; i++)
#pragma unroll
        for (int q = 0; q < 4; q++) oacc[i][q] = 0.f;
    float mrow[2] = {-1e30f, -1e30f};
    float lrow[2] = {0.f, 0.f};

    const int NT = 2 * (qt + 1);
    const int wr = qb + wid * 16;
    const float scale = 0.125f;

    for (int kt = 0; kt < NT; kt++) {
        const int s = kt & 1;
        const int kb = kt * 64;
        if (kt + 1 < NT) {
            load_kv(kt + 1, s ^ 1);
            CPCOMMIT();
            CPWAIT(1);
        } else {
            CPWAIT(0);
        }
        __syncthreads();

        const uint32_t KH = STG0 + s * FSTAGE_B;
        const uint32_t KL = KH + KVSUB_B;
        const uint32_t VH = KH + 2 * KVSUB_B;
        const uint32_t VL = KH + 3 * KVSUB_B;

        // ---- S = Q K^T (3-pass) ----
        float sacc[8][4];
#pragma unroll
        for (int i = 0; i < 8; i++)
#pragma unroll
            for (int q = 0; q < 4; q++) sacc[i][q] = 0.f;

        {
            int br = lane & 7;
            int bsel = lane >> 4;
            int bksel = (lane >> 3) & 1;
#pragma unroll
            for (int ks = 0; ks < 4; ks++) {
                int bc = 2 * ks + bksel;
#pragma unroll
                for (int fp = 0; fp < 4; fp++) {
                    int krow = fp * 16 + bsel * 8 + br;
                    uint32_t t0, t1, t2, t3, u0, u1, u2, u3;
                    LDSM4(t0, t1, t2, t3, sw128(KH, krow, bc));
                    LDSM4(u0, u1, u2, u3, sw128(KL, krow, bc));
                    MMA16816R(sacc[2 * fp],     qhiF[ks], t0, t1);
                    MMA16816R(sacc[2 * fp],     qloF[ks], t0, t1);
                    MMA16816R(sacc[2 * fp],     qhiF[ks], u0, u1);
                    MMA16816R(sacc[2 * fp + 1], qhiF[ks], t2, t3);
                    MMA16816R(sacc[2 * fp + 1], qloF[ks], t2, t3);
                    MMA16816R(sacc[2 * fp + 1], qhiF[ks], u2, u3);
                }
            }
        }

        // ---- scale + causal mask ----
        const bool need_mask = (kb + 63 > wr);
#pragma unroll
        for (int fn = 0; fn < 8; fn++)
#pragma unroll
            for (int q = 0; q < 4; q++) sacc[fn][q] *= scale;
        if (need_mask) {
#pragma unroll
            for (int fn = 0; fn < 8; fn++)
#pragma unroll
                for (int q = 0; q < 4; q++) {
                    int kc = kb + fn * 8 + (lane & 3) * 2 + (q & 1);
                    int qr = wr + (lane >> 2) + (q >> 1) * 8;
                    if (kc > qr) sacc[fn][q] = -1e30f;
                }
        }

        // ---- online softmax (per row pair) ----
#pragma unroll
        for (int r = 0; r < 2; r++) {
            float rmax = -1e30f;
#pragma unroll
            for (int fn = 0; fn < 8; fn++) {
                rmax = fmaxf(rmax, sacc[fn][2 * r]);
                rmax = fmaxf(rmax, sacc[fn][2 * r + 1]);
            }
            rmax = fmaxf(rmax, __shfl_xor_sync(0xffffffffu, rmax, 1));
            rmax = fmaxf(rmax, __shfl_xor_sync(0xffffffffu, rmax, 2));

            float mn = fmaxf(mrow[r], rmax);
            float alpha = __expf(mrow[r] - mn);
            mrow[r] = mn;

            float rs = 0.f;
#pragma unroll
            for (int fn = 0; fn < 8; fn++) {
                float p0 = __expf(sacc[fn][2 * r] - mn);
                float p1 = __expf(sacc[fn][2 * r + 1] - mn);
                sacc[fn][2 * r] = p0;
                sacc[fn][2 * r + 1] = p1;
                rs += p0 + p1;
            }
            rs += __shfl_xor_sync(0xffffffffu, rs, 1);
            rs += __shfl_xor_sync(0xffffffffu, rs, 2);
            lrow[r] = lrow[r] * alpha + rs;

#pragma unroll
            for (int fn = 0; fn < 8; fn++) {
                oacc[fn][2 * r]     *= alpha;
                oacc[fn][2 * r + 1] *= alpha;
            }
        }

        // ---- O += P V (P split on the fly; 3-pass) ----
        {
            int g = lane >> 3;
            int vr_off = (g & 1) * 8 + (lane & 7);
            int vc_off = g >> 1;
#pragma unroll
            for (int ks = 0; ks < 4; ks++) {
                // P a-fragments from sacc tiles 2ks, 2ks+1
                uint32_t phiF[4], ploF[4];
                pack_split(sacc[2 * ks][0],     sacc[2 * ks][1],     phiF[0], ploF[0]);
                pack_split(sacc[2 * ks][2],     sacc[2 * ks][3],     phiF[1], ploF[1]);
                pack_split(sacc[2 * ks + 1][0], sacc[2 * ks + 1][1], phiF[2], ploF[2]);
                pack_split(sacc[2 * ks + 1][2], sacc[2 * ks + 1][3], phiF[3], ploF[3]);

                int vrow = ks * 16 + vr_off;
#pragma unroll
                for (int fv = 0; fv < 4; fv++) {
                    int vchunk = 2 * fv + vc_off;
                    uint32_t t0, t1, t2, t3, u0, u1, u2, u3;
                    LDSM4T(t0, t1, t2, t3, sw128(VH, vrow, vchunk));
                    LDSM4T(u0, u1, u2, u3, sw128(VL, vrow, vchunk));
                    MMA16816R(oacc[2 * fv],     phiF, t0, t1);
                    MMA16816R(oacc[2 * fv],     ploF, t0, t1);
                    MMA16816R(oacc[2 * fv],     phiF, u0, u1);
                    MMA16816R(oacc[2 * fv + 1], phiF, t2, t3);
                    MMA16816R(oacc[2 * fv + 1], ploF, t2, t3);
                    MMA16816R(oacc[2 * fv + 1], phiF, u2, u3);
                }
            }
        }
        __syncthreads();
    }

    // ---- epilogue: normalize, split, store ----
#pragma unroll
    for (int r = 0; r < 2; r++) {
        float inv = 1.f / lrow[r];
        int row = wr + (lane >> 2) + 8 * r;
#pragma unroll
        for (int fn = 0; fn < 8; fn++) {
            int col = h * HD + fn * 8 + (lane & 3) * 2;
            float x0 = oacc[fn][2 * r] * inv;
            float x1 = oacc[fn][2 * r + 1] * inv;
            uint32_t hv, lv;
            pack_split(x0, x1, hv, lv);
            size_t e = (size_t)(b * TT + row) * DD + col;
            *(uint32_t*)&g_Ahi[e] = hv;
            *(uint32_t*)&g_Alo[e] = lv;
        }
    }
}

// ---------------------------------------------------------------------------
// Launch
// ---------------------------------------------------------------------------
extern "C" void kernel_launch(void* const* d_in, const int* in_sizes, int n_in,
                              void* d_out, int out_size)
{
    const float* x  = (const float*)d_in[0];
    const float* Wq = (const float*)d_in[1];
    const float* Wk = (const float*)d_in[2];
    const float* Wv = (const float*)d_in[3];
    const float* Wo = (const float*)d_in[4];
    float* out = (float*)d_out;

    __nv_bfloat16 *xh, *xl, *wqh, *wql, *wkh, *wkl, *wvh, *wvl, *woh, *wol;
    __nv_bfloat16 *qh, *ql, *kh, *kl, *vh, *vl, *ah, *al;
    cudaGetSymbolAddress((void**)&xh, g_xhi);   cudaGetSymbolAddress((void**)&xl, g_xlo);
    cudaGetSymbolAddress((void**)&wqh, g_Wqhi); cudaGetSymbolAddress((void**)&wql, g_Wqlo);
    cudaGetSymbolAddress((void**)&wkh, g_Wkhi); cudaGetSymbolAddress((void**)&wkl, g_Wklo);
    cudaGetSymbolAddress((void**)&wvh, g_Wvhi); cudaGetSymbolAddress((void**)&wvl, g_Wvlo);
    cudaGetSymbolAddress((void**)&woh, g_Wohi); cudaGetSymbolAddress((void**)&wol, g_Wolo);
    cudaGetSymbolAddress((void**)&qh, g_Qhi);   cudaGetSymbolAddress((void**)&ql, g_Qlo);
    cudaGetSymbolAddress((void**)&kh, g_Khi);   cudaGetSymbolAddress((void**)&kl, g_Klo);
    cudaGetSymbolAddress((void**)&vh, g_Vhi);   cudaGetSymbolAddress((void**)&vl, g_Vlo);
    cudaGetSymbolAddress((void**)&ah, g_Ahi);   cudaGetSymbolAddress((void**)&al, g_Alo);

    cudaFuncSetAttribute(gemm_tc_kernel<true>,
                         cudaFuncAttributeMaxDynamicSharedMemorySize, GEMM_SMEM);
    cudaFuncSetAttribute(gemm_tc_kernel<false>,
                         cudaFuncAttributeMaxDynamicSharedMemorySize, GEMM_SMEM);
    cudaFuncSetAttribute(flash_tc_kernel,
                         cudaFuncAttributeMaxDynamicSharedMemorySize, FLASH_SMEM);

    // fp32 -> bf16 hi/lo splits (inputs only)
    const int n_x  = MTOT * DD / 4, n_wq = DD * DD / 4, n_wk = DKV * DD / 4;
    split_kernel<<<(n_x  + 255) / 256, 256>>>(x,  xh,  xl,  n_x);
    split_kernel<<<(n_wq + 255) / 256, 256>>>(Wq, wqh, wql, n_wq);
    split_kernel<<<(n_wk + 255) / 256, 256>>>(Wk, wkh, wkl, n_wk);
    split_kernel<<<(n_wk + 255) / 256, 256>>>(Wv, wvh, wvl, n_wk);
    split_kernel<<<(n_wq + 255) / 256, 256>>>(Wo, woh, wol, n_wq);

    // Projections -> split bf16 outputs
    gemm_tc_kernel<true><<<dim3(DD / 128, MTOT / 128), 256, GEMM_SMEM>>>(
        xh, xl, wqh, wql, nullptr, qh, ql, MTOT, DD, DD);
    gemm_tc_kernel<true><<<dim3(DKV / 128, MTOT / 128), 256, GEMM_SMEM>>>(
        xh, xl, wkh, wkl, nullptr, kh, kl, MTOT, DKV, DD);
    gemm_tc_kernel<true><<<dim3(DKV / 128, MTOT / 128), 256, GEMM_SMEM>>>(
        xh, xl, wvh, wvl, nullptr, vh, vl, MTOT, DKV, DD);

    // Tensor-core causal GQA flash attention -> split bf16 A
    flash_tc_kernel<<<dim3(TT / 128, HH, BB), 256, FLASH_SMEM>>>();

    // Output projection -> fp32 out
    gemm_tc_kernel<false><<<dim3(DD / 128, MTOT / 128), 256, GEMM_SMEM>>>(
        ah, al, woh, wol, out, nullptr, nullptr, MTOT, DD, DD);
}

// round 6
// speedup vs baseline: 3.0878x; 1.0073x over previous
#include <cuda_runtime.h>
#include <cuda_bf16.h>
#include <cstdint>
#include <math.h>

// Problem constants
#define BB   2
#define TT   2048
#define DD   2048
#define HH   32
#define KVH  8
#define HD   64
#define MTOT (BB*TT)      // 4096
#define DKV  (KVH*HD)     // 512

// ---------------------------------------------------------------------------
// Scratch (__device__ globals; no allocation allowed) — all split bf16 pairs
// ---------------------------------------------------------------------------
__device__ __nv_bfloat16 g_xhi[(size_t)MTOT * DD],  g_xlo[(size_t)MTOT * DD];
__device__ __nv_bfloat16 g_Wqhi[(size_t)DD * DD],   g_Wqlo[(size_t)DD * DD];
__device__ __nv_bfloat16 g_Wkhi[(size_t)DKV * DD],  g_Wklo[(size_t)DKV * DD];
__device__ __nv_bfloat16 g_Wvhi[(size_t)DKV * DD],  g_Wvlo[(size_t)DKV * DD];
__device__ __nv_bfloat16 g_Wohi[(size_t)DD * DD],   g_Wolo[(size_t)DD * DD];

__device__ __nv_bfloat16 g_Qhi[(size_t)MTOT * DD],  g_Qlo[(size_t)MTOT * DD];
__device__ __nv_bfloat16 g_Khi[(size_t)MTOT * DKV], g_Klo[(size_t)MTOT * DKV];
__device__ __nv_bfloat16 g_Vhi[(size_t)MTOT * DKV], g_Vlo[(size_t)MTOT * DKV];
__device__ __nv_bfloat16 g_Ahi[(size_t)MTOT * DD],  g_Alo[(size_t)MTOT * DD];

// ---------------------------------------------------------------------------
// Helpers (portable PTX only: cp.async / ldmatrix / mma.sync)
// ---------------------------------------------------------------------------
__device__ __forceinline__ uint32_t s2u(const void* p) {
    return (uint32_t)__cvta_generic_to_shared(p);
}

#define CP16(sa, ga) \
    asm volatile("cp.async.cg.shared.global [%0], [%1], 16;" :: "r"(sa), "l"(ga) : "memory")
#define CPCOMMIT()  asm volatile("cp.async.commit_group;" ::: "memory")
#define CPWAIT(n)   asm volatile("cp.async.wait_group %0;" :: "n"(n) : "memory")

#define LDSM4(r0, r1, r2, r3, addr) \
    asm volatile("ldmatrix.sync.aligned.m8n8.x4.shared.b16 {%0,%1,%2,%3}, [%4];" \
        : "=r"(r0), "=r"(r1), "=r"(r2), "=r"(r3) : "r"(addr))

#define LDSM4T(r0, r1, r2, r3, addr) \
    asm volatile("ldmatrix.sync.aligned.m8n8.x4.trans.shared.b16 {%0,%1,%2,%3}, [%4];" \
        : "=r"(r0), "=r"(r1), "=r"(r2), "=r"(r3) : "r"(addr))

#define MMA16816(d, a, b) \
    asm volatile("mma.sync.aligned.m16n8k16.row.col.f32.bf16.bf16.f32 " \
        "{%0,%1,%2,%3}, {%4,%5,%6,%7}, {%8,%9}, {%0,%1,%2,%3};" \
        : "+f"((d)[0]), "+f"((d)[1]), "+f"((d)[2]), "+f"((d)[3]) \
        : "r"((a)[0]), "r"((a)[1]), "r"((a)[2]), "r"((a)[3]), "r"((b)[0]), "r"((b)[1]))

#define MMA16816R(d, a, b0v, b1v) \
    asm volatile("mma.sync.aligned.m16n8k16.row.col.f32.bf16.bf16.f32 " \
        "{%0,%1,%2,%3}, {%4,%5,%6,%7}, {%8,%9}, {%0,%1,%2,%3};" \
        : "+f"((d)[0]), "+f"((d)[1]), "+f"((d)[2]), "+f"((d)[3]) \
        : "r"((a)[0]), "r"((a)[1]), "r"((a)[2]), "r"((a)[3]), "r"(b0v), "r"(b1v))

// 64B-row swizzle (GEMM tiles)
__device__ __forceinline__ uint32_t sw_addr(uint32_t base, int row, int chunk) {
    return base + row * 64 + ((chunk ^ ((row >> 1) & 3)) << 4);
}
// 128B-row swizzle (flash tiles)
__device__ __forceinline__ uint32_t sw128(uint32_t base, int row, int chunk) {
    return base + row * 128 + ((chunk ^ (row & 7)) << 4);
}

// split fp32 pair -> packed bf16x2 (hi, lo)
__device__ __forceinline__ void pack_split(float x0, float x1, uint32_t& hi, uint32_t& lo) {
    __nv_bfloat16 h0 = __float2bfloat16(x0);
    __nv_bfloat16 h1 = __float2bfloat16(x1);
    __nv_bfloat16 l0 = __float2bfloat16(x0 - __bfloat162float(h0));
    __nv_bfloat16 l1 = __float2bfloat16(x1 - __bfloat162float(h1));
    __nv_bfloat162 hp(h0, h1), lp(l0, l1);
    hi = *(uint32_t*)&hp;
    lo = *(uint32_t*)&lp;
}

// ---------------------------------------------------------------------------
// fp32 -> (bf16 hi, bf16 lo) split kernel (inputs only)
// ---------------------------------------------------------------------------
__global__ __launch_bounds__(256)
void split_kernel(const float* __restrict__ src, __nv_bfloat16* __restrict__ hi,
                  __nv_bfloat16* __restrict__ lo, int n4)
{
    int i = blockIdx.x * blockDim.x + threadIdx.x;
    if (i >= n4) return;
    float4 v = ((const float4*)src)[i];
    uint32_t h0, l0, h1, l1;
    pack_split(v.x, v.y, h0, l0);
    pack_split(v.z, v.w, h1, l1);
    ((uint2*)hi)[i] = make_uint2(h0, h1);
    ((uint2*)lo)[i] = make_uint2(l0, l1);
}

// ---------------------------------------------------------------------------
// mma.sync GEMM:  C = A * B^T  (3-pass bf16 split precision)
// CTA 128x128, BK=32, 4-stage cp.async, ONE __syncthreads per chunk.
// 8 warps (2x4), warp tile 64x32.
// ---------------------------------------------------------------------------
#define STAGES      4
#define TILE_B      8192
#define STAGE_B     (4 * TILE_B)            // 32 KB
#define GEMM_SMEM   (STAGES * STAGE_B)      // 128 KB

template<bool SPLIT>
__global__ __launch_bounds__(256)
void gemm_tc_kernel(const __nv_bfloat16* __restrict__ Ahi, const __nv_bfloat16* __restrict__ Alo,
                    const __nv_bfloat16* __restrict__ Bhi, const __nv_bfloat16* __restrict__ Blo,
                    float* __restrict__ C,
                    __nv_bfloat16* __restrict__ Chi, __nv_bfloat16* __restrict__ Clo,
                    int M, int N, int K)
{
    extern __shared__ __align__(128) char smem[];
    const uint32_t sbase = s2u(smem);

    const int tid = threadIdx.x;
    const int wid = tid >> 5;
    const int lane = tid & 31;
    const int bm = blockIdx.y * 128;
    const int bn = blockIdx.x * 128;

    const int wm = (wid & 1) * 64;
    const int wn = (wid >> 1) * 32;

    const char* srcs[4] = {(const char*)Ahi, (const char*)Alo,
                           (const char*)Bhi, (const char*)Blo};
    const size_t rowstride = (size_t)K * 2;

    const int NC = K >> 5;

    auto load_chunk = [&](int c, int s) {
        const uint32_t sb = sbase + s * STAGE_B;
        const size_t k0b = (size_t)c * 64;
#pragma unroll
        for (int t = 0; t < 4; t++) {
            const int rbase = (t < 2) ? bm : bn;
            const char* src = srcs[t];
#pragma unroll
            for (int j = 0; j < 2; j++) {
                int i = tid + j * 256;
                int r = i >> 2;
                int ck = i & 3;
                const char* ga = src + (size_t)(rbase + r) * rowstride + k0b + ck * 16;
                CP16(sw_addr(sb + t * TILE_B, r, ck), ga);
            }
        }
    };

    float acc[4][4][4];
#pragma unroll
    for (int i = 0; i < 4; i++)
#pragma unroll
        for (int j = 0; j < 4; j++)
#pragma unroll
            for (int q = 0; q < 4; q++) acc[i][j][q] = 0.f;

    // prefill 3 stages (NC >= 16 always here)
    load_chunk(0, 0); CPCOMMIT();
    load_chunk(1, 1); CPCOMMIT();
    load_chunk(2, 2); CPCOMMIT();

    for (int c = 0; c < NC; c++) {
        const int s = c & 3;
        CPWAIT(2);                 // chunk c resident (pending: c+1, c+2)
        __syncthreads();           // single barrier per chunk

        if (c + 3 < NC) {          // overwrites stage (c-1)&3 — reads done pre-barrier
            load_chunk(c + 3, (c + 3) & 3);
            CPCOMMIT();
        }

        const uint32_t sb   = sbase + s * STAGE_B;
        const uint32_t sAhi = sb;
        const uint32_t sAlo = sb + TILE_B;
        const uint32_t sBhi = sb + 2 * TILE_B;
        const uint32_t sBlo = sb + 3 * TILE_B;

#pragma unroll
        for (int ks = 0; ks < 2; ks++) {
            const int ckbase = ks * 2;

            uint32_t ahi[4][4], alo[4][4], bhi[4][2], blo[4][2];
            {
                int ar = (lane & 15);
                int ac = ckbase + (lane >> 4);
#pragma unroll
                for (int fm = 0; fm < 4; fm++) {
                    uint32_t ad = sw_addr(sAhi, wm + fm * 16 + ar, ac);
                    LDSM4(ahi[fm][0], ahi[fm][1], ahi[fm][2], ahi[fm][3], ad);
                    uint32_t ad2 = sw_addr(sAlo, wm + fm * 16 + ar, ac);
                    LDSM4(alo[fm][0], alo[fm][1], alo[fm][2], alo[fm][3], ad2);
                }
                int br = (lane & 7);
                int bsel = (lane >> 4);
                int bc = ckbase + ((lane >> 3) & 1);
#pragma unroll
                for (int fp = 0; fp < 2; fp++) {
                    uint32_t bd = sw_addr(sBhi, wn + (fp * 2 + bsel) * 8 + br, bc);
                    uint32_t t0, t1, t2, t3;
                    LDSM4(t0, t1, t2, t3, bd);
                    bhi[fp * 2][0] = t0; bhi[fp * 2][1] = t1;
                    bhi[fp * 2 + 1][0] = t2; bhi[fp * 2 + 1][1] = t3;
                    uint32_t bd2 = sw_addr(sBlo, wn + (fp * 2 + bsel) * 8 + br, bc);
                    LDSM4(t0, t1, t2, t3, bd2);
                    blo[fp * 2][0] = t0; blo[fp * 2][1] = t1;
                    blo[fp * 2 + 1][0] = t2; blo[fp * 2 + 1][1] = t3;
                }
            }

#pragma unroll
            for (int fm = 0; fm < 4; fm++)
#pragma unroll
                for (int fn = 0; fn < 4; fn++) {
                    MMA16816(acc[fm][fn], ahi[fm], bhi[fn]);
                    MMA16816(acc[fm][fn], alo[fm], bhi[fn]);
                    MMA16816(acc[fm][fn], ahi[fm], blo[fn]);
                }
        }
        // no trailing barrier: next iteration's top barrier closes the hazard
    }

    const int lr = lane >> 2;
    const int lc = (lane & 3) * 2;
#pragma unroll
    for (int fm = 0; fm < 4; fm++) {
#pragma unroll
        for (int fn = 0; fn < 4; fn++) {
            int r0 = bm + wm + fm * 16 + lr;
            int cc = bn + wn + fn * 8 + lc;
            if (SPLIT) {
                uint32_t h, l;
                pack_split(acc[fm][fn][0], acc[fm][fn][1], h, l);
                *(uint32_t*)&Chi[(size_t)r0 * N + cc] = h;
                *(uint32_t*)&Clo[(size_t)r0 * N + cc] = l;
                pack_split(acc[fm][fn][2], acc[fm][fn][3], h, l);
                *(uint32_t*)&Chi[(size_t)(r0 + 8) * N + cc] = h;
                *(uint32_t*)&Clo[(size_t)(r0 + 8) * N + cc] = l;
            } else {
                *(float2*)&C[(size_t)r0 * N + cc]       = make_float2(acc[fm][fn][0], acc[fm][fn][1]);
                *(float2*)&C[(size_t)(r0 + 8) * N + cc] = make_float2(acc[fm][fn][2], acc[fm][fn][3]);
            }
        }
    }
}

// ---------------------------------------------------------------------------
// Tensor-core flash attention (split-precision bf16 mma).
// Grid (T/128, H, B), 256 threads = 8 warps x 16 q-rows.
// KV tile 64, 3-stage cp.async ring, ONE __syncthreads per KV tile.
// SMEM: Qhi+Qlo 32KB + 3 stages x 32KB = 128KB.
// ---------------------------------------------------------------------------
#define QTILE_B   16384
#define KVSUB_B   8192
#define FSTAGE_B  (4 * KVSUB_B)
#define FSTAGES   3
#define FLASH_SMEM (2 * QTILE_B + FSTAGES * FSTAGE_B)

__global__ __launch_bounds__(256, 1)
void flash_tc_kernel()
{
    extern __shared__ __align__(128) char fsm[];
    const uint32_t sbase = s2u(fsm);
    const uint32_t QHI = sbase;
    const uint32_t QLO = sbase + QTILE_B;
    const uint32_t STG0 = sbase + 2 * QTILE_B;

    const int qt  = blockIdx.x;
    const int h   = blockIdx.y;
    const int b   = blockIdx.z;
    const int kvh = h >> 2;
    const int qb  = qt * 128;

    const int tid = threadIdx.x;
    const int wid = tid >> 5;
    const int lane = tid & 31;

    // ---- load Q tile (hi/lo) ----
#pragma unroll
    for (int j = 0; j < 4; j++) {
        int i = tid + j * 256;
        int r = i >> 3;
        int ck = i & 7;
        size_t e = (size_t)(b * TT + qb + r) * DD + h * HD + ck * 8;
        CP16(sw128(QHI, r, ck), (const char*)&g_Qhi[e]);
        CP16(sw128(QLO, r, ck), (const char*)&g_Qlo[e]);
    }
    CPCOMMIT();

    auto load_kv = [&](int kt, int s) {
        const uint32_t sb = STG0 + s * FSTAGE_B;
#pragma unroll
        for (int j = 0; j < 2; j++) {
            int i = tid + j * 256;
            int r = i >> 3;
            int ck = i & 7;
            size_t e = (size_t)(b * TT + kt * 64 + r) * DKV + kvh * HD + ck * 8;
            uint32_t so = sw128(sb, r, ck);
            CP16(so,               (const char*)&g_Khi[e]);
            CP16(so + KVSUB_B,     (const char*)&g_Klo[e]);
            CP16(so + 2 * KVSUB_B, (const char*)&g_Vhi[e]);
            CP16(so + 3 * KVSUB_B, (const char*)&g_Vlo[e]);
        }
    };

    const int NT = 2 * (qt + 1);

    // prefill: kv0, kv1 (NT >= 2 always)
    load_kv(0, 0); CPCOMMIT();
    if (NT > 1) { load_kv(1, 1); CPCOMMIT(); }

    // Q resident (pending <= kv0, kv1)
    CPWAIT(2);
    __syncthreads();

    // ---- Q fragments (register-resident) ----
    uint32_t qhiF[4][4], qloF[4][4];
    {
        int ar = lane & 15;
        int ac = lane >> 4;
#pragma unroll
        for (int ks = 0; ks < 4; ks++) {
            uint32_t ad = sw128(QHI, wid * 16 + ar, 2 * ks + ac);
            LDSM4(qhiF[ks][0], qhiF[ks][1], qhiF[ks][2], qhiF[ks][3], ad);
            uint32_t ad2 = sw128(QLO, wid * 16 + ar, 2 * ks + ac);
            LDSM4(qloF[ks][0], qloF[ks][1], qloF[ks][2], qloF[ks][3], ad2);
        }
    }

    float oacc[8][4];
#pragma unroll
    for (int i = 0; i < 8; i++)
#pragma unroll
        for (int q = 0; q < 4; q++) oacc[i][q] = 0.f;
    float mrow[2] = {-1e30f, -1e30f};
    float lrow[2] = {0.f, 0.f};

    const int wr = qb + wid * 16;
    const float scale = 0.125f;

    for (int kt = 0; kt < NT; kt++) {
        const int s = kt % FSTAGES;
        const int kb = kt * 64;

        CPWAIT(1);                 // tile kt resident (pending: kt+1)
        __syncthreads();           // single barrier per tile

        if (kt + 2 < NT) {         // overwrites stage (kt-1)%3 — reads done pre-barrier
            load_kv(kt + 2, (kt + 2) % FSTAGES);
            CPCOMMIT();
        }

        const uint32_t KH = STG0 + s * FSTAGE_B;
        const uint32_t KL = KH + KVSUB_B;
        const uint32_t VH = KH + 2 * KVSUB_B;
        const uint32_t VL = KH + 3 * KVSUB_B;

        // ---- S = Q K^T (3-pass) ----
        float sacc[8][4];
#pragma unroll
        for (int i = 0; i < 8; i++)
#pragma unroll
            for (int q = 0; q < 4; q++) sacc[i][q] = 0.f;

        {
            int br = lane & 7;
            int bsel = lane >> 4;
            int bksel = (lane >> 3) & 1;
#pragma unroll
            for (int ks = 0; ks < 4; ks++) {
                int bc = 2 * ks + bksel;
#pragma unroll
                for (int fp = 0; fp < 4; fp++) {
                    int krow = fp * 16 + bsel * 8 + br;
                    uint32_t t0, t1, t2, t3, u0, u1, u2, u3;
                    LDSM4(t0, t1, t2, t3, sw128(KH, krow, bc));
                    LDSM4(u0, u1, u2, u3, sw128(KL, krow, bc));
                    MMA16816R(sacc[2 * fp],     qhiF[ks], t0, t1);
                    MMA16816R(sacc[2 * fp],     qloF[ks], t0, t1);
                    MMA16816R(sacc[2 * fp],     qhiF[ks], u0, u1);
                    MMA16816R(sacc[2 * fp + 1], qhiF[ks], t2, t3);
                    MMA16816R(sacc[2 * fp + 1], qloF[ks], t2, t3);
                    MMA16816R(sacc[2 * fp + 1], qhiF[ks], u2, u3);
                }
            }
        }

        // ---- scale + causal mask ----
        const bool need_mask = (kb + 63 > wr);
#pragma unroll
        for (int fn = 0; fn < 8; fn++)
#pragma unroll
            for (int q = 0; q < 4; q++) sacc[fn][q] *= scale;
        if (need_mask) {
#pragma unroll
            for (int fn = 0; fn < 8; fn++)
#pragma unroll
                for (int q = 0; q < 4; q++) {
                    int kc = kb + fn * 8 + (lane & 3) * 2 + (q & 1);
                    int qr = wr + (lane >> 2) + (q >> 1) * 8;
                    if (kc > qr) sacc[fn][q] = -1e30f;
                }
        }

        // ---- online softmax ----
#pragma unroll
        for (int r = 0; r < 2; r++) {
            float rmax = -1e30f;
#pragma unroll
            for (int fn = 0; fn < 8; fn++) {
                rmax = fmaxf(rmax, sacc[fn][2 * r]);
                rmax = fmaxf(rmax, sacc[fn][2 * r + 1]);
            }
            rmax = fmaxf(rmax, __shfl_xor_sync(0xffffffffu, rmax, 1));
            rmax = fmaxf(rmax, __shfl_xor_sync(0xffffffffu, rmax, 2));

            float mn = fmaxf(mrow[r], rmax);
            float alpha = __expf(mrow[r] - mn);
            mrow[r] = mn;

            float rs = 0.f;
#pragma unroll
            for (int fn = 0; fn < 8; fn++) {
                float p0 = __expf(sacc[fn][2 * r] - mn);
                float p1 = __expf(sacc[fn][2 * r + 1] - mn);
                sacc[fn][2 * r] = p0;
                sacc[fn][2 * r + 1] = p1;
                rs += p0 + p1;
            }
            rs += __shfl_xor_sync(0xffffffffu, rs, 1);
            rs += __shfl_xor_sync(0xffffffffu, rs, 2);
            lrow[r] = lrow[r] * alpha + rs;

#pragma unroll
            for (int fn = 0; fn < 8; fn++) {
                oacc[fn][2 * r]     *= alpha;
                oacc[fn][2 * r + 1] *= alpha;
            }
        }

        // ---- O += P V (P split on the fly; 3-pass) ----
        {
            int g = lane >> 3;
            int vr_off = (g & 1) * 8 + (lane & 7);
            int vc_off = g >> 1;
#pragma unroll
            for (int ks = 0; ks < 4; ks++) {
                uint32_t phiF[4], ploF[4];
                pack_split(sacc[2 * ks][0],     sacc[2 * ks][1],     phiF[0], ploF[0]);
                pack_split(sacc[2 * ks][2],     sacc[2 * ks][3],     phiF[1], ploF[1]);
                pack_split(sacc[2 * ks + 1][0], sacc[2 * ks + 1][1], phiF[2], ploF[2]);
                pack_split(sacc[2 * ks + 1][2], sacc[2 * ks + 1][3], phiF[3], ploF[3]);

                int vrow = ks * 16 + vr_off;
#pragma unroll
                for (int fv = 0; fv < 4; fv++) {
                    int vchunk = 2 * fv + vc_off;
                    uint32_t t0, t1, t2, t3, u0, u1, u2, u3;
                    LDSM4T(t0, t1, t2, t3, sw128(VH, vrow, vchunk));
                    LDSM4T(u0, u1, u2, u3, sw128(VL, vrow, vchunk));
                    MMA16816R(oacc[2 * fv],     phiF, t0, t1);
                    MMA16816R(oacc[2 * fv],     ploF, t0, t1);
                    MMA16816R(oacc[2 * fv],     phiF, u0, u1);
                    MMA16816R(oacc[2 * fv + 1], phiF, t2, t3);
                    MMA16816R(oacc[2 * fv + 1], ploF, t2, t3);
                    MMA16816R(oacc[2 * fv + 1], phiF, u2, u3);
                }
            }
        }
        // no trailing barrier (3-stage ring; top barrier closes the hazard)
    }

    // ---- epilogue: normalize, split, store ----
#pragma unroll
    for (int r = 0; r < 2; r++) {
        float inv = 1.f / lrow[r];
        int row = wr + (lane >> 2) + 8 * r;
#pragma unroll
        for (int fn = 0; fn < 8; fn++) {
            int col = h * HD + fn * 8 + (lane & 3) * 2;
            float x0 = oacc[fn][2 * r] * inv;
            float x1 = oacc[fn][2 * r + 1] * inv;
            uint32_t hv, lv;
            pack_split(x0, x1, hv, lv);
            size_t e = (size_t)(b * TT + row) * DD + col;
            *(uint32_t*)&g_Ahi[e] = hv;
            *(uint32_t*)&g_Alo[e] = lv;
        }
    }
}

// ---------------------------------------------------------------------------
// Launch
// ---------------------------------------------------------------------------
extern "C" void kernel_launch(void* const* d_in, const int* in_sizes, int n_in,
                              void* d_out, int out_size)
{
    const float* x  = (const float*)d_in[0];
    const float* Wq = (const float*)d_in[1];
    const float* Wk = (const float*)d_in[2];
    const float* Wv = (const float*)d_in[3];
    const float* Wo = (const float*)d_in[4];
    float* out = (float*)d_out;

    __nv_bfloat16 *xh, *xl, *wqh, *wql, *wkh, *wkl, *wvh, *wvl, *woh, *wol;
    __nv_bfloat16 *qh, *ql, *kh, *kl, *vh, *vl, *ah, *al;
    cudaGetSymbolAddress((void**)&xh, g_xhi);   cudaGetSymbolAddress((void**)&xl, g_xlo);
    cudaGetSymbolAddress((void**)&wqh, g_Wqhi); cudaGetSymbolAddress((void**)&wql, g_Wqlo);
    cudaGetSymbolAddress((void**)&wkh, g_Wkhi); cudaGetSymbolAddress((void**)&wkl, g_Wklo);
    cudaGetSymbolAddress((void**)&wvh, g_Wvhi); cudaGetSymbolAddress((void**)&wvl, g_Wvlo);
    cudaGetSymbolAddress((void**)&woh, g_Wohi); cudaGetSymbolAddress((void**)&wol, g_Wolo);
    cudaGetSymbolAddress((void**)&qh, g_Qhi);   cudaGetSymbolAddress((void**)&ql, g_Qlo);
    cudaGetSymbolAddress((void**)&kh, g_Khi);   cudaGetSymbolAddress((void**)&kl, g_Klo);
    cudaGetSymbolAddress((void**)&vh, g_Vhi);   cudaGetSymbolAddress((void**)&vl, g_Vlo);
    cudaGetSymbolAddress((void**)&ah, g_Ahi);   cudaGetSymbolAddress((void**)&al, g_Alo);

    cudaFuncSetAttribute(gemm_tc_kernel<true>,
                         cudaFuncAttributeMaxDynamicSharedMemorySize, GEMM_SMEM);
    cudaFuncSetAttribute(gemm_tc_kernel<false>,
                         cudaFuncAttributeMaxDynamicSharedMemorySize, GEMM_SMEM);
    cudaFuncSetAttribute(flash_tc_kernel,
                         cudaFuncAttributeMaxDynamicSharedMemorySize, FLASH_SMEM);

    // fp32 -> bf16 hi/lo splits (inputs only)
    const int n_x  = MTOT * DD / 4, n_wq = DD * DD / 4, n_wk = DKV * DD / 4;
    split_kernel<<<(n_x  + 255) / 256, 256>>>(x,  xh,  xl,  n_x);
    split_kernel<<<(n_wq + 255) / 256, 256>>>(Wq, wqh, wql, n_wq);
    split_kernel<<<(n_wk + 255) / 256, 256>>>(Wk, wkh, wkl, n_wk);
    split_kernel<<<(n_wk + 255) / 256, 256>>>(Wv, wvh, wvl, n_wk);
    split_kernel<<<(n_wq + 255) / 256, 256>>>(Wo, woh, wol, n_wq);

    // Projections -> split bf16 outputs
    gemm_tc_kernel<true><<<dim3(DD / 128, MTOT / 128), 256, GEMM_SMEM>>>(
        xh, xl, wqh, wql, nullptr, qh, ql, MTOT, DD, DD);
    gemm_tc_kernel<true><<<dim3(DKV / 128, MTOT / 128), 256, GEMM_SMEM>>>(
        xh, xl, wkh, wkl, nullptr, kh, kl, MTOT, DKV, DD);
    gemm_tc_kernel<true><<<dim3(DKV / 128, MTOT / 128), 256, GEMM_SMEM>>>(
        xh, xl, wvh, wvl, nullptr, vh, vl, MTOT, DKV, DD);

    // Tensor-core causal GQA flash attention -> split bf16 A
    flash_tc_kernel<<<dim3(TT / 128, HH, BB), 256, FLASH_SMEM>>>();

    // Output projection -> fp32 out
    gemm_tc_kernel<false><<<dim3(DD / 128, MTOT / 128), 256, GEMM_SMEM>>>(
        ah, al, woh, wol, out, nullptr, nullptr, MTOT, DD, DD);
}